// round 11
// baseline (speedup 1.0000x reference)
#include <cuda_runtime.h>
#include <cuda_bf16.h>
#include <math.h>
#include <stdint.h>

#define BATCH 8
#define CDIM 384
#define NHEAD 8
#define CH 48
#define HW 16384
#define EPS 1e-12f

// ---------------- warp-MMA + cp.async helpers ----------------
__device__ __forceinline__ uint32_t smem_u32(const void* p) {
    uint32_t a;
    asm("{ .reg .u64 t; cvta.to.shared.u64 t, %1; cvt.u32.u64 %0, t; }" : "=r"(a) : "l"(p));
    return a;
}
__device__ __forceinline__ void ldm_x4(uint32_t* r, uint32_t addr) {
    asm volatile("ldmatrix.sync.aligned.m8n8.x4.shared.b16 {%0,%1,%2,%3}, [%4];"
                 : "=r"(r[0]), "=r"(r[1]), "=r"(r[2]), "=r"(r[3]) : "r"(addr));
}
__device__ __forceinline__ void ldm_x4_trans(uint32_t* r, uint32_t addr) {
    asm volatile("ldmatrix.sync.aligned.m8n8.x4.trans.shared.b16 {%0,%1,%2,%3}, [%4];"
                 : "=r"(r[0]), "=r"(r[1]), "=r"(r[2]), "=r"(r[3]) : "r"(addr));
}
__device__ __forceinline__ void mma_bf16(float* d, const uint32_t* a, const uint32_t* b) {
    asm volatile(
        "mma.sync.aligned.m16n8k16.row.col.f32.bf16.bf16.f32 "
        "{%0,%1,%2,%3}, {%4,%5,%6,%7}, {%8,%9}, {%0,%1,%2,%3};"
        : "+f"(d[0]), "+f"(d[1]), "+f"(d[2]), "+f"(d[3])
        : "r"(a[0]), "r"(a[1]), "r"(a[2]), "r"(a[3]), "r"(b[0]), "r"(b[1]));
}
__device__ __forceinline__ void cp_async16(uint32_t saddr, const void* gptr) {
    asm volatile("cp.async.cg.shared.global [%0], [%1], 16;" :: "r"(saddr), "l"(gptr));
}
#define CP_COMMIT() asm volatile("cp.async.commit_group;")
#define CP_WAIT0()  asm volatile("cp.async.wait_group 0;")

// ---------------- scratch ----------------
__device__ float g_G [(size_t)BATCH * CDIM * CDIM];
__device__ float g_Rq[(size_t)BATCH * CDIM * CDIM];
__device__ float g_Rk[(size_t)BATCH * CDIM * CDIM];
__device__ float g_invq[BATCH * CDIM];
__device__ float g_invk[BATCH * CDIM];
__device__ float g_S [BATCH * NHEAD * CH * CH];
__device__ float g_A [BATCH * NHEAD * CH * CH];

__device__ __nv_bfloat16 g_xhi [(size_t)BATCH * CDIM * HW];   // [b][c][n]
__device__ __nv_bfloat16 g_xlo [(size_t)BATCH * CDIM * HW];
__device__ __nv_bfloat16 g_Ghi [(size_t)BATCH * CDIM * CDIM];
__device__ __nv_bfloat16 g_Glo [(size_t)BATCH * CDIM * CDIM];
__device__ __nv_bfloat16 g_BsThi[(size_t)BATCH * CDIM * CDIM]; // [b][m][c]
__device__ __nv_bfloat16 g_BsTlo[(size_t)BATCH * CDIM * CDIM];
__device__ __nv_bfloat16 g_Mhi [(size_t)BATCH * CDIM * CDIM];
__device__ __nv_bfloat16 g_Mlo [(size_t)BATCH * CDIM * CDIM];
__device__ __nv_bfloat16 g_Whi [3 * CDIM * CDIM];
__device__ __nv_bfloat16 g_Wlo [3 * CDIM * CDIM];

// ---------------- converts ----------------
__global__ void convert_plain(const float* __restrict__ x) {
    size_t i = ((size_t)blockIdx.x * 256 + threadIdx.x) * 8;
    float4 v0 = *(const float4*)(x + i);
    float4 v1 = *(const float4*)(x + i + 4);
    float v[8] = {v0.x, v0.y, v0.z, v0.w, v1.x, v1.y, v1.z, v1.w};
    __align__(16) __nv_bfloat16 hh[8], ll[8];
#pragma unroll
    for (int j = 0; j < 8; ++j) {
        __nv_bfloat16 h = __float2bfloat16(v[j]);
        hh[j] = h;
        ll[j] = __float2bfloat16(v[j] - __bfloat162float(h));
    }
    *(uint4*)(g_xhi + i) = *(const uint4*)hh;
    *(uint4*)(g_xlo + i) = *(const uint4*)ll;
}

__global__ void convert_W(const float* __restrict__ wq, const float* __restrict__ wk,
                          const float* __restrict__ wo) {
    int i = blockIdx.x * 256 + threadIdx.x;
    if (i >= CDIM * CDIM) return;
    const float* srcs[3] = {wq, wk, wo};
#pragma unroll
    for (int m = 0; m < 3; ++m) {
        float v = srcs[m][i];
        __nv_bfloat16 h = __float2bfloat16(v);
        g_Whi[m * CDIM * CDIM + i] = h;
        g_Wlo[m * CDIM * CDIM + i] = __float2bfloat16(v - __bfloat162float(h));
    }
}

__global__ void zero_G_kernel() {
    size_t i = (size_t)blockIdx.x * 256 + threadIdx.x;
    if (i < (size_t)BATCH * CDIM * CDIM) g_G[i] = 0.f;
}

__global__ void mirror_convert_G() {
    size_t i = (size_t)blockIdx.x * 256 + threadIdx.x;
    if (i >= (size_t)BATCH * CDIM * CDIM) return;
    size_t bb = i / (CDIM * CDIM);
    int rc = (int)(i % (CDIM * CDIM));
    int r = rc / CDIM, c = rc % CDIM;
    float v;
    if ((r >> 7) > (c >> 7)) {
        v = g_G[bb * CDIM * CDIM + (size_t)c * CDIM + r];
        g_G[i] = v;
    } else {
        v = g_G[i];
    }
    __nv_bfloat16 h = __float2bfloat16(v);
    g_Ghi[i] = h;
    g_Glo[i] = __float2bfloat16(v - __bfloat162float(h));
}

// ---------------- panel geometry ----------------
#define PROWB 80
#define PANEL 30720              // 384 rows * 80 B (one of hi/lo)
#define S_STAGE (2 * PANEL)      // 61440
#define S_SMEM (2 * S_STAGE)     // 122880

// ---------------- syrk: per-CTA 128 x (384-128*mt) upper row-panel ----------------
template<int NP>   // NP = n-granule pairs per warp (6/4/2); warp n-width = NP*16
__device__ __forceinline__ void syrk_body(int mtile, int kb, int b, uint32_t sb) {
    const int tid = threadIdx.x, lane = tid & 31, wid = tid >> 5;
    const int wrow = wid & 1, wcol = wid >> 1;    // 2 x 4 warp grid
    const int rows = CDIM - mtile * 128;          // panel rows (n-cols of output)
    const int nW = NP * 16;

    const __nv_bfloat16* Ph = g_xhi + ((size_t)(b * CDIM + mtile * 128)) * HW;
    const __nv_bfloat16* Pl = g_xlo + ((size_t)(b * CDIM + mtile * 128)) * HW;

    float acc[4][2 * NP][4];
#pragma unroll
    for (int i = 0; i < 4; ++i)
#pragma unroll
        for (int j = 0; j < 2 * NP; ++j)
#pragma unroll
            for (int k = 0; k < 4; ++k) acc[i][j][k] = 0.f;

    auto issue = [&](uint32_t sdst, int k0) {
        for (int idx = tid; idx < rows * 8; idx += 256) {
            int r = idx >> 3, g = idx & 7, gg = g & 3;
            uint32_t so = sdst + (g < 4 ? 0u : (uint32_t)PANEL) + r * PROWB + gg * 16;
            const __nv_bfloat16* src = (g < 4 ? Ph : Pl) + (size_t)r * HW + k0 + gg * 8;
            cp_async16(so, src);
        }
    };

    issue(sb, kb);
    CP_COMMIT();

    for (int ch = 0; ch < 32; ++ch) {
        CP_WAIT0();
        __syncthreads();
        if (ch < 31) {
            issue(sb + ((ch + 1) & 1) * S_STAGE, kb + (ch + 1) * 32);
            CP_COMMIT();
        }
        const uint32_t sbase = sb + (ch & 1) * S_STAGE;
#pragma unroll
        for (int kk = 0; kk < 2; ++kk) {
            uint32_t ah[4][4], al[4][4];
#pragma unroll
            for (int mi = 0; mi < 4; ++mi) {
                uint32_t aoff = (uint32_t)(wrow * 64 + mi * 16 + (lane & 15)) * PROWB
                              + (lane >> 4) * 16 + kk * 32;
                ldm_x4(ah[mi], sbase + aoff);
                ldm_x4(al[mi], sbase + PANEL + aoff);
            }
#pragma unroll
            for (int np = 0; np < NP; ++np) {
                uint32_t bh[4], bl[4];
                uint32_t boff = (uint32_t)(wcol * nW + np * 16 + ((lane >> 4) << 3) + (lane & 7)) * PROWB
                              + ((lane >> 3) & 1) * 16 + kk * 32;
                ldm_x4(bh, sbase + boff);
                ldm_x4(bl, sbase + PANEL + boff);
#pragma unroll
                for (int mi = 0; mi < 4; ++mi) {
                    mma_bf16(acc[mi][np * 2 + 0], ah[mi], &bh[0]);
                    mma_bf16(acc[mi][np * 2 + 1], ah[mi], &bh[2]);
                    mma_bf16(acc[mi][np * 2 + 0], ah[mi], &bl[0]);
                    mma_bf16(acc[mi][np * 2 + 1], ah[mi], &bl[2]);
                    mma_bf16(acc[mi][np * 2 + 0], al[mi], &bh[0]);
                    mma_bf16(acc[mi][np * 2 + 1], al[mi], &bh[2]);
                }
            }
        }
    }

    float* Gp = g_G + (size_t)b * CDIM * CDIM;
    const int r0 = mtile * 128 + wrow * 64;
    const int c0 = mtile * 128 + wcol * nW;
#pragma unroll
    for (int mi = 0; mi < 4; ++mi)
#pragma unroll
        for (int f = 0; f < 2 * NP; ++f) {
            int row = r0 + mi * 16 + (lane >> 2);
            int col = c0 + f * 8 + (lane & 3) * 2;
            atomicAdd(&Gp[(size_t)row * CDIM + col],           acc[mi][f][0]);
            atomicAdd(&Gp[(size_t)row * CDIM + col + 1],       acc[mi][f][1]);
            atomicAdd(&Gp[(size_t)(row + 8) * CDIM + col],     acc[mi][f][2]);
            atomicAdd(&Gp[(size_t)(row + 8) * CDIM + col + 1], acc[mi][f][3]);
        }
}

__global__ __launch_bounds__(256) void syrk_mma() {
    extern __shared__ __align__(16) char sm[];
    const uint32_t sb = smem_u32(sm);
    const int mtile = blockIdx.x;
    const int kb = blockIdx.y * 1024;
    const int b = blockIdx.z;
    if (mtile == 0)      syrk_body<6>(0, kb, b, sb);
    else if (mtile == 1) syrk_body<4>(1, kb, b, sb);
    else                 syrk_body<2>(2, kb, b, sb);
}

// ---------------- wgemm (unchanged from R10) ----------------
#define ROWB 80
#define TILE_BYTES (128 * ROWB)
#define OFF_AH 0
#define OFF_AL (1 * TILE_BYTES)
#define OFF_BH (2 * TILE_BYTES)
#define OFF_BL (3 * TILE_BYTES)
#define STAGE_BYTES (4 * TILE_BYTES)
#define PIPE_SMEM (2 * STAGE_BYTES)

__device__ __forceinline__ void issue_stage(uint32_t sdst,
    const __nv_bfloat16* Ah, const __nv_bfloat16* Al,
    const __nv_bfloat16* Bh, const __nv_bfloat16* Bl,
    size_t strideA, size_t strideB, int k0, int tid)
{
#pragma unroll
    for (int t = 0; t < 2; ++t) {
        int idx = t * 256 + tid;
        int r = idx >> 2, g = idx & 3;
        uint32_t so = (uint32_t)(r * ROWB + g * 16);
        size_t goA = (size_t)r * strideA + k0 + g * 8;
        size_t goB = (size_t)r * strideB + k0 + g * 8;
        cp_async16(sdst + OFF_AH + so, Ah + goA);
        cp_async16(sdst + OFF_AL + so, Al + goA);
        cp_async16(sdst + OFF_BH + so, Bh + goB);
        cp_async16(sdst + OFF_BL + so, Bl + goB);
    }
}

__device__ __forceinline__ void mma_chunk(uint32_t sbase, int lane, int wm, int wn,
                                          float acc[4][4][4]) {
#pragma unroll
    for (int kk = 0; kk < 2; ++kk) {
        uint32_t a_hi[4][4], a_lo[4][4], b_hi[2][4], b_lo[2][4];
        const uint32_t arow = (uint32_t)(wm * 64 + (lane & 15));
        const uint32_t acol = ((lane >> 4) * 16) + kk * 32;
#pragma unroll
        for (int mi = 0; mi < 4; ++mi) {
            uint32_t off = (arow + mi * 16) * ROWB + acol;
            ldm_x4(a_hi[mi], sbase + OFF_AH + off);
            ldm_x4(a_lo[mi], sbase + OFF_AL + off);
        }
        const uint32_t brow = (uint32_t)(wn * 32 + ((lane >> 4) << 3) + (lane & 7));
        const uint32_t bcol = (((lane >> 3) & 1) * 16) + kk * 32;
#pragma unroll
        for (int nj = 0; nj < 2; ++nj) {
            uint32_t off = (brow + nj * 16) * ROWB + bcol;
            ldm_x4(b_hi[nj], sbase + OFF_BH + off);
            ldm_x4(b_lo[nj], sbase + OFF_BL + off);
        }
#pragma unroll
        for (int mi = 0; mi < 4; ++mi)
#pragma unroll
            for (int nj = 0; nj < 2; ++nj) {
                mma_bf16(acc[mi][nj * 2 + 0], a_hi[mi], &b_hi[nj][0]);
                mma_bf16(acc[mi][nj * 2 + 1], a_hi[mi], &b_hi[nj][2]);
                mma_bf16(acc[mi][nj * 2 + 0], a_hi[mi], &b_lo[nj][0]);
                mma_bf16(acc[mi][nj * 2 + 1], a_hi[mi], &b_lo[nj][2]);
                mma_bf16(acc[mi][nj * 2 + 0], a_lo[mi], &b_hi[nj][0]);
                mma_bf16(acc[mi][nj * 2 + 1], a_lo[mi], &b_hi[nj][2]);
            }
    }
}

__global__ __launch_bounds__(256) void wgemm_mma(int mode) {
    extern __shared__ __align__(16) char sm[];
    const int tid = threadIdx.x, lane = tid & 31, wid = tid >> 5;
    const int wm = wid & 1, wn = wid >> 1;
    const int o0 = (blockIdx.x % 3) * 128;
    const int j0 = (blockIdx.x / 3) * 128;
    const int b = blockIdx.y;
    const int which = blockIdx.z;
    const size_t CC = (size_t)CDIM * CDIM;

    const int widx = mode ? 2 : which;
    const __nv_bfloat16* Ah = g_Whi + (size_t)widx * CC + (size_t)o0 * CDIM;
    const __nv_bfloat16* Al = g_Wlo + (size_t)widx * CC + (size_t)o0 * CDIM;
    const __nv_bfloat16* Bh = (mode ? g_BsThi : g_Ghi) + (size_t)b * CC + (size_t)j0 * CDIM;
    const __nv_bfloat16* Bl = (mode ? g_BsTlo : g_Glo) + (size_t)b * CC + (size_t)j0 * CDIM;

    float acc[4][4][4];
#pragma unroll
    for (int i = 0; i < 4; ++i)
#pragma unroll
        for (int j = 0; j < 4; ++j)
#pragma unroll
            for (int k = 0; k < 4; ++k) acc[i][j][k] = 0.f;

    const uint32_t sb = smem_u32(sm);
    issue_stage(sb, Ah, Al, Bh, Bl, CDIM, CDIM, 0, tid);
    CP_COMMIT();

    for (int ch = 0; ch < 12; ++ch) {
        CP_WAIT0();
        __syncthreads();
        if (ch < 11) {
            issue_stage(sb + ((ch + 1) & 1) * STAGE_BYTES, Ah, Al, Bh, Bl,
                        CDIM, CDIM, (ch + 1) * 32, tid);
            CP_COMMIT();
        }
        mma_chunk(sb + (ch & 1) * STAGE_BYTES, lane, wm, wn, acc);
    }

    if (mode == 0) {
        float* C = (which ? g_Rk : g_Rq) + b * CC;
#pragma unroll
        for (int mi = 0; mi < 4; ++mi)
#pragma unroll
            for (int f = 0; f < 4; ++f) {
                int o = o0 + wm * 64 + mi * 16 + (lane >> 2);
                int j = j0 + wn * 32 + f * 8 + (lane & 3) * 2;
                *(float2*)&C[(size_t)o * CDIM + j] =
                    make_float2(acc[mi][f][0], acc[mi][f][1]);
                *(float2*)&C[(size_t)(o + 8) * CDIM + j] =
                    make_float2(acc[mi][f][2], acc[mi][f][3]);
            }
    } else {
#pragma unroll
        for (int mi = 0; mi < 4; ++mi)
#pragma unroll
            for (int f = 0; f < 4; ++f) {
                int o = o0 + wm * 64 + mi * 16 + (lane >> 2);
                int j = j0 + wn * 32 + f * 8 + (lane & 3) * 2;
#pragma unroll
                for (int half = 0; half < 2; ++half) {
                    float v0 = acc[mi][f][half * 2 + 0];
                    float v1 = acc[mi][f][half * 2 + 1];
                    __nv_bfloat16 h0 = __float2bfloat16(v0);
                    __nv_bfloat16 h1 = __float2bfloat16(v1);
                    __nv_bfloat16 l0 = __float2bfloat16(v0 - __bfloat162float(h0));
                    __nv_bfloat16 l1 = __float2bfloat16(v1 - __bfloat162float(h1));
                    size_t off = b * CC + (size_t)(o + half * 8) * CDIM + j;
                    *(__nv_bfloat162*)(g_Mhi + off) = __nv_bfloat162(h0, h1);
                    *(__nv_bfloat162*)(g_Mlo + off) = __nv_bfloat162(l0, l1);
                }
            }
    }
}

// ---------------- out = M @ x : CTA = 384o x 128n, A = full M panel ----------------
#define O_BROWB 272
#define O_B (2 * PANEL)                 // 61440 (A hi + A lo first)
#define OBTILE (32 * O_BROWB)           // 8704
#define O_STAGE (O_B + 2 * OBTILE)      // 78848
#define OUT_SMEM (2 * O_STAGE)          // 157696

__global__ __launch_bounds__(256) void out_mma(float* __restrict__ out) {
    extern __shared__ __align__(16) char sm[];
    const int tid = threadIdx.x, lane = tid & 31, wid = tid >> 5;
    const int wrow = wid & 3, wcol = wid >> 2;    // 4 x 2 warp grid: 96 x 64 tiles
    const int ntile = blockIdx.x;
    const int b = blockIdx.y;
    const size_t CC = (size_t)CDIM * CDIM;

    const __nv_bfloat16* Ahp = g_Mhi + (size_t)b * CC;
    const __nv_bfloat16* Alp = g_Mlo + (size_t)b * CC;
    const __nv_bfloat16* Xh = g_xhi + (size_t)b * CDIM * HW + (size_t)ntile * 128;
    const __nv_bfloat16* Xl = g_xlo + (size_t)b * CDIM * HW + (size_t)ntile * 128;

    float acc[6][8][4];
#pragma unroll
    for (int i = 0; i < 6; ++i)
#pragma unroll
        for (int j = 0; j < 8; ++j)
#pragma unroll
            for (int k = 0; k < 4; ++k) acc[i][j][k] = 0.f;

    const uint32_t sb = smem_u32(sm);

    auto issue = [&](uint32_t sdst, int cbase) {
        // A: full 384-row M panel, 32 c per chunk
#pragma unroll
        for (int t = 0; t < 12; ++t) {
            int idx = t * 256 + tid;
            int r = idx >> 3, g = idx & 7, gg = g & 3;
            uint32_t so = sdst + (g < 4 ? 0u : (uint32_t)PANEL) + r * PROWB + gg * 16;
            const __nv_bfloat16* src = (g < 4 ? Ahp : Alp) + (size_t)r * CDIM + cbase + gg * 8;
            cp_async16(so, src);
        }
        // B: 32 c-rows x 128 n (trans layout)
#pragma unroll
        for (int t = 0; t < 4; ++t) {
            int idx = t * 256 + tid;
            int r = idx >> 5, g = idx & 31, gg = g & 15;
            uint32_t so = sdst + O_B + (g < 16 ? 0u : (uint32_t)OBTILE) + r * O_BROWB + gg * 16;
            const __nv_bfloat16* src = (g < 16 ? Xh : Xl) + (size_t)(cbase + r) * HW + gg * 8;
            cp_async16(so, src);
        }
    };

    issue(sb, 0);
    CP_COMMIT();

    for (int ch = 0; ch < 12; ++ch) {
        CP_WAIT0();
        __syncthreads();
        if (ch < 11) {
            issue(sb + ((ch + 1) & 1) * O_STAGE, (ch + 1) * 32);
            CP_COMMIT();
        }
        const uint32_t sbase = sb + (ch & 1) * O_STAGE;
#pragma unroll
        for (int kk = 0; kk < 2; ++kk) {
            uint32_t bh[4][4], bl[4][4];
            const uint32_t brow = (uint32_t)(kk * 16 + (lane & 7) + ((lane >> 3) & 1) * 8);
#pragma unroll
            for (int np = 0; np < 4; ++np) {
                uint32_t bcol = (uint32_t)(wcol * 64 + np * 16 + (lane >> 4) * 8) * 2;
                uint32_t off = O_B + brow * O_BROWB + bcol;
                ldm_x4_trans(bh[np], sbase + off);
                ldm_x4_trans(bl[np], sbase + off + OBTILE);
            }
#pragma unroll
            for (int mi = 0; mi < 6; ++mi) {
                uint32_t ah[4], al[4];
                uint32_t aoff = (uint32_t)(wrow * 96 + mi * 16 + (lane & 15)) * PROWB
                              + (lane >> 4) * 16 + kk * 32;
                ldm_x4(ah, sbase + aoff);
                ldm_x4(al, sbase + PANEL + aoff);
#pragma unroll
                for (int np = 0; np < 4; ++np) {
                    mma_bf16(acc[mi][np * 2 + 0], ah, &bh[np][0]);
                    mma_bf16(acc[mi][np * 2 + 1], ah, &bh[np][2]);
                    mma_bf16(acc[mi][np * 2 + 0], ah, &bl[np][0]);
                    mma_bf16(acc[mi][np * 2 + 1], ah, &bl[np][2]);
                    mma_bf16(acc[mi][np * 2 + 0], al, &bh[np][0]);
                    mma_bf16(acc[mi][np * 2 + 1], al, &bh[np][2]);
                }
            }
        }
    }

    const int o0 = wrow * 96;
    const int n0 = ntile * 128 + wcol * 64;
#pragma unroll
    for (int mi = 0; mi < 6; ++mi)
#pragma unroll
        for (int f = 0; f < 8; ++f) {
            int o = o0 + mi * 16 + (lane >> 2);
            int n = n0 + f * 8 + (lane & 3) * 2;
            *(float2*)&out[((size_t)b * CDIM + o) * HW + n] =
                make_float2(acc[mi][f][0], acc[mi][f][1]);
            *(float2*)&out[((size_t)b * CDIM + o + 8) * HW + n] =
                make_float2(acc[mi][f][2], acc[mi][f][3]);
        }
}

// ---------------- fp32 tail ----------------
__global__ void norms_kernel(const float* __restrict__ wq, const float* __restrict__ wk) {
    const int which = blockIdx.x;
    const int b = blockIdx.y;
    const float* R = (which ? g_Rk : g_Rq) + (size_t)b * CDIM * CDIM;
    const float* W = which ? wk : wq;
    float* inv = (which ? g_invk : g_invq) + b * CDIM;
    const int lane = threadIdx.x & 31;
    const int wd = threadIdx.x >> 5;
    for (int r = wd; r < CDIM; r += 12) {
        float s = 0.f;
        for (int j = lane; j < CDIM; j += 32)
            s = fmaf(R[(size_t)r * CDIM + j], W[(size_t)r * CDIM + j], s);
#pragma unroll
        for (int o = 16; o; o >>= 1) s += __shfl_xor_sync(0xffffffffu, s, o);
        if (lane == 0) inv[r] = 1.f / fmaxf(sqrtf(fmaxf(s, 0.f)), EPS);
    }
}

__global__ __launch_bounds__(256) void s_kernel(const float* __restrict__ wk) {
    const int bh = blockIdx.x;
    const int b = bh >> 3;
    const int h = bh & 7;
    const int tid = threadIdx.x;

    __shared__ float qs[CH][68];
    __shared__ float ks[CH][68];

    const int c0 = (tid >> 4) * 3;
    const int d0 = (tid & 15) * 3;

    float acc[3][3];
#pragma unroll
    for (int i = 0; i < 3; ++i)
#pragma unroll
        for (int j = 0; j < 3; ++j) acc[i][j] = 0.f;

    const float* Rq = g_Rq + (size_t)b * CDIM * CDIM + (size_t)(h * CH) * CDIM;
    const float* Wk = wk + (size_t)(h * CH) * CDIM;

    for (int ck = 0; ck < 6; ++ck) {
        const int koff = ck * 64;
#pragma unroll
        for (int t = 0; t < 3; ++t) {
            int idx = t * 256 + tid;
            int row = idx >> 4;
            int col = (idx & 15) * 4;
            *(float4*)&qs[row][col] = *(const float4*)(Rq + (size_t)row * CDIM + koff + col);
            *(float4*)&ks[row][col] = *(const float4*)(Wk + (size_t)row * CDIM + koff + col);
        }
        __syncthreads();
#pragma unroll 8
        for (int kk = 0; kk < 64; ++kk) {
            float q0 = qs[c0 + 0][kk], q1 = qs[c0 + 1][kk], q2 = qs[c0 + 2][kk];
            float k0 = ks[d0 + 0][kk], k1 = ks[d0 + 1][kk], k2 = ks[d0 + 2][kk];
            acc[0][0] = fmaf(q0, k0, acc[0][0]);
            acc[0][1] = fmaf(q0, k1, acc[0][1]);
            acc[0][2] = fmaf(q0, k2, acc[0][2]);
            acc[1][0] = fmaf(q1, k0, acc[1][0]);
            acc[1][1] = fmaf(q1, k1, acc[1][1]);
            acc[1][2] = fmaf(q1, k2, acc[1][2]);
            acc[2][0] = fmaf(q2, k0, acc[2][0]);
            acc[2][1] = fmaf(q2, k1, acc[2][1]);
            acc[2][2] = fmaf(q2, k2, acc[2][2]);
        }
        __syncthreads();
    }

    float* Sb = g_S + (size_t)bh * CH * CH;
#pragma unroll
    for (int i = 0; i < 3; ++i)
#pragma unroll
        for (int j = 0; j < 3; ++j)
            Sb[(c0 + i) * CH + (d0 + j)] = acc[i][j];
}

__global__ void attn_softmax_kernel(const float* __restrict__ temperature) {
    const int bh = blockIdx.x;
    const int b = bh >> 3;
    const int h = bh & 7;
    const int c = threadIdx.x;
    if (c >= CH) return;

    const float t = temperature[h];
    const float sq = g_invq[b * CDIM + h * CH + c] * t;
    const float* Srow = g_S + (size_t)bh * CH * CH + c * CH;
    const float* ik = g_invk + b * CDIM + h * CH;

    float v[CH];
    float m = -1e30f;
#pragma unroll
    for (int d = 0; d < CH; ++d) {
        v[d] = Srow[d] * sq * ik[d];
        m = fmaxf(m, v[d]);
    }
    float sum = 0.f;
#pragma unroll
    for (int d = 0; d < CH; ++d) {
        v[d] = __expf(v[d] - m);
        sum += v[d];
    }
    float inv = 1.f / sum;
    float* Arow = g_A + (size_t)bh * CH * CH + c * CH;
#pragma unroll
    for (int d = 0; d < CH; ++d) Arow[d] = v[d] * inv;
}

__global__ __launch_bounds__(384) void bstack_T(const float* __restrict__ wv) {
    const int bh = blockIdx.x;
    const int b = bh >> 3;
    const int h = bh & 7;

    __shared__ float As[CH * CH];
    const float* Ahp = g_A + (size_t)bh * CH * CH;
    for (int i = threadIdx.x; i < CH * CH; i += 384) As[i] = Ahp[i];
    __syncthreads();

    const int m = threadIdx.x;
    float acc[CH];
#pragma unroll
    for (int i = 0; i < CH; ++i) acc[i] = 0.f;

    const float* wvp = wv + (size_t)(h * CH) * CDIM + m;
    for (int d = 0; d < CH; ++d) {
        float wvv = wvp[(size_t)d * CDIM];
#pragma unroll
        for (int cp = 0; cp < CH; ++cp) acc[cp] = fmaf(As[cp * CH + d], wvv, acc[cp]);
    }
    size_t base = ((size_t)b * CDIM + m) * CDIM + h * CH;
    __align__(16) __nv_bfloat16 hh[CH], ll[CH];
#pragma unroll
    for (int cp = 0; cp < CH; ++cp) {
        __nv_bfloat16 hv = __float2bfloat16(acc[cp]);
        hh[cp] = hv;
        ll[cp] = __float2bfloat16(acc[cp] - __bfloat162float(hv));
    }
#pragma unroll
    for (int q = 0; q < CH / 4; ++q) {
        *(uint2*)(g_BsThi + base + q * 4) = *(const uint2*)(hh + q * 4);
        *(uint2*)(g_BsTlo + base + q * 4) = *(const uint2*)(ll + q * 4);
    }
}

// ---------------- launcher ----------------
extern "C" void kernel_launch(void* const* d_in, const int* in_sizes, int n_in,
                              void* d_out, int out_size) {
    const float* x    = (const float*)d_in[0];
    const float* wq   = (const float*)d_in[1];
    const float* wk   = (const float*)d_in[2];
    const float* wv   = (const float*)d_in[3];
    const float* wo   = (const float*)d_in[4];
    const float* temp = (const float*)d_in[5];
    float* out = (float*)d_out;

    cudaFuncSetAttribute(syrk_mma, cudaFuncAttributeMaxDynamicSharedMemorySize, S_SMEM);
    cudaFuncSetAttribute(wgemm_mma, cudaFuncAttributeMaxDynamicSharedMemorySize, PIPE_SMEM);
    cudaFuncSetAttribute(out_mma, cudaFuncAttributeMaxDynamicSharedMemorySize, OUT_SMEM);

    const size_t CC = (size_t)CDIM * CDIM;
    const int nG = (int)(((size_t)BATCH * CC + 255) / 256);

    convert_plain<<<24576, 256>>>(x);
    convert_W<<<(CDIM * CDIM + 255) / 256, 256>>>(wq, wk, wo);
    zero_G_kernel<<<nG, 256>>>();
    syrk_mma<<<dim3(3, 16, BATCH), 256, S_SMEM>>>();
    mirror_convert_G<<<nG, 256>>>();

    wgemm_mma<<<dim3(9, BATCH, 2), 256, PIPE_SMEM>>>(0);   // Rq, Rk

    norms_kernel<<<dim3(2, BATCH), 384>>>(wq, wk);
    s_kernel<<<BATCH * NHEAD, 256>>>(wk);
    attn_softmax_kernel<<<BATCH * NHEAD, 64>>>(temp);
    bstack_T<<<BATCH * NHEAD, 384>>>(wv);

    wgemm_mma<<<dim3(9, BATCH, 1), 256, PIPE_SMEM>>>(1);   // Mhi/Mlo

    out_mma<<<dim3(HW / 128, BATCH), 256, OUT_SMEM>>>(out);
}

// round 12
// speedup vs baseline: 1.0837x; 1.0837x over previous
#include <cuda_runtime.h>
#include <cuda_bf16.h>
#include <math.h>
#include <stdint.h>

#define BATCH 8
#define CDIM 384
#define NHEAD 8
#define CH 48
#define HW 16384
#define EPS 1e-12f

// ---------------- warp-MMA + cp.async helpers (plain sm_80+ PTX) ----------------
__device__ __forceinline__ uint32_t smem_u32(const void* p) {
    uint32_t a;
    asm("{ .reg .u64 t; cvta.to.shared.u64 t, %1; cvt.u32.u64 %0, t; }" : "=r"(a) : "l"(p));
    return a;
}
__device__ __forceinline__ void ldm_x4(uint32_t* r, uint32_t addr) {
    asm volatile("ldmatrix.sync.aligned.m8n8.x4.shared.b16 {%0,%1,%2,%3}, [%4];"
                 : "=r"(r[0]), "=r"(r[1]), "=r"(r[2]), "=r"(r[3]) : "r"(addr));
}
__device__ __forceinline__ void ldm_x4_trans(uint32_t* r, uint32_t addr) {
    asm volatile("ldmatrix.sync.aligned.m8n8.x4.trans.shared.b16 {%0,%1,%2,%3}, [%4];"
                 : "=r"(r[0]), "=r"(r[1]), "=r"(r[2]), "=r"(r[3]) : "r"(addr));
}
__device__ __forceinline__ void mma_bf16(float* d, const uint32_t* a, const uint32_t* b) {
    asm volatile(
        "mma.sync.aligned.m16n8k16.row.col.f32.bf16.bf16.f32 "
        "{%0,%1,%2,%3}, {%4,%5,%6,%7}, {%8,%9}, {%0,%1,%2,%3};"
        : "+f"(d[0]), "+f"(d[1]), "+f"(d[2]), "+f"(d[3])
        : "r"(a[0]), "r"(a[1]), "r"(a[2]), "r"(a[3]), "r"(b[0]), "r"(b[1]));
}
__device__ __forceinline__ void cp_async16(uint32_t saddr, const void* gptr) {
    asm volatile("cp.async.cg.shared.global [%0], [%1], 16;" :: "r"(saddr), "l"(gptr));
}
#define CP_COMMIT() asm volatile("cp.async.commit_group;")
#define CP_WAIT0()  asm volatile("cp.async.wait_group 0;")

// ---------------- scratch ----------------
__device__ float g_G [(size_t)BATCH * CDIM * CDIM];
__device__ float g_Rq[(size_t)BATCH * CDIM * CDIM];
__device__ float g_Rk[(size_t)BATCH * CDIM * CDIM];
__device__ float g_invq[BATCH * CDIM];
__device__ float g_invk[BATCH * CDIM];
__device__ float g_S [BATCH * NHEAD * CH * CH];
__device__ float g_A [BATCH * NHEAD * CH * CH];

__device__ __nv_bfloat16 g_xhi [(size_t)BATCH * CDIM * HW];   // [b][c][n]
__device__ __nv_bfloat16 g_xlo [(size_t)BATCH * CDIM * HW];
__device__ __nv_bfloat16 g_Ghi [(size_t)BATCH * CDIM * CDIM];
__device__ __nv_bfloat16 g_Glo [(size_t)BATCH * CDIM * CDIM];
__device__ __nv_bfloat16 g_BsThi[(size_t)BATCH * CDIM * CDIM]; // [b][m][c]
__device__ __nv_bfloat16 g_BsTlo[(size_t)BATCH * CDIM * CDIM];
__device__ __nv_bfloat16 g_Mhi [(size_t)BATCH * CDIM * CDIM];
__device__ __nv_bfloat16 g_Mlo [(size_t)BATCH * CDIM * CDIM];
__device__ __nv_bfloat16 g_Whi [3 * CDIM * CDIM];
__device__ __nv_bfloat16 g_Wlo [3 * CDIM * CDIM];

// ---------------- converts ----------------
__global__ void convert_plain(const float* __restrict__ x) {
    size_t i = ((size_t)blockIdx.x * 256 + threadIdx.x) * 8;
    float4 v0 = *(const float4*)(x + i);
    float4 v1 = *(const float4*)(x + i + 4);
    float v[8] = {v0.x, v0.y, v0.z, v0.w, v1.x, v1.y, v1.z, v1.w};
    __align__(16) __nv_bfloat16 hh[8], ll[8];
#pragma unroll
    for (int j = 0; j < 8; ++j) {
        __nv_bfloat16 h = __float2bfloat16(v[j]);
        hh[j] = h;
        ll[j] = __float2bfloat16(v[j] - __bfloat162float(h));
    }
    *(uint4*)(g_xhi + i) = *(const uint4*)hh;
    *(uint4*)(g_xlo + i) = *(const uint4*)ll;
}

__global__ void convert_W(const float* __restrict__ wq, const float* __restrict__ wk,
                          const float* __restrict__ wo) {
    int i = blockIdx.x * 256 + threadIdx.x;
    if (i >= CDIM * CDIM) return;
    const float* srcs[3] = {wq, wk, wo};
#pragma unroll
    for (int m = 0; m < 3; ++m) {
        float v = srcs[m][i];
        __nv_bfloat16 h = __float2bfloat16(v);
        g_Whi[m * CDIM * CDIM + i] = h;
        g_Wlo[m * CDIM * CDIM + i] = __float2bfloat16(v - __bfloat162float(h));
    }
}

__global__ void zero_G_kernel() {
    size_t i = (size_t)blockIdx.x * 256 + threadIdx.x;
    if (i < (size_t)BATCH * CDIM * CDIM) g_G[i] = 0.f;
}

__global__ void mirror_convert_G() {
    size_t i = (size_t)blockIdx.x * 256 + threadIdx.x;
    if (i >= (size_t)BATCH * CDIM * CDIM) return;
    size_t bb = i / (CDIM * CDIM);
    int rc = (int)(i % (CDIM * CDIM));
    int r = rc / CDIM, c = rc % CDIM;
    float v;
    if ((r >> 7) > (c >> 7)) {
        v = g_G[bb * CDIM * CDIM + (size_t)c * CDIM + r];
        g_G[i] = v;
    } else {
        v = g_G[i];
    }
    __nv_bfloat16 h = __float2bfloat16(v);
    g_Ghi[i] = h;
    g_Glo[i] = __float2bfloat16(v - __bfloat162float(h));
}

// ---------------- MMA tile geometry ----------------
#define ROWB 80
#define TILE_BYTES (128 * ROWB)
#define OFF_AH 0
#define OFF_AL (1 * TILE_BYTES)
#define OFF_BH (2 * TILE_BYTES)
#define OFF_BL (3 * TILE_BYTES)
#define STAGE_BYTES (4 * TILE_BYTES)   // 40960
#define PIPE_SMEM (2 * STAGE_BYTES)    // 81920

// Issue one stage; loadB=false skips the B tiles (diagonal syrk pairs: B ≡ A).
__device__ __forceinline__ void issue_stage(uint32_t sdst,
    const __nv_bfloat16* Ah, const __nv_bfloat16* Al,
    const __nv_bfloat16* Bh, const __nv_bfloat16* Bl,
    size_t strideA, size_t strideB, int k0, int tid, bool loadB)
{
#pragma unroll
    for (int t = 0; t < 2; ++t) {
        int idx = t * 256 + tid;
        int r = idx >> 2, g = idx & 3;
        uint32_t so = (uint32_t)(r * ROWB + g * 16);
        size_t goA = (size_t)r * strideA + k0 + g * 8;
        cp_async16(sdst + OFF_AH + so, Ah + goA);
        cp_async16(sdst + OFF_AL + so, Al + goA);
        if (loadB) {
            size_t goB = (size_t)r * strideB + k0 + g * 8;
            cp_async16(sdst + OFF_BH + so, Bh + goB);
            cp_async16(sdst + OFF_BL + so, Bl + goB);
        }
    }
}

// offB_h/offB_l select where the B fragments live (OFF_BH/OFF_BL or OFF_AH/OFF_AL on diag).
__device__ __forceinline__ void mma_chunk(uint32_t sbase, int lane, int wm, int wn,
                                          float acc[4][4][4],
                                          uint32_t offB_h, uint32_t offB_l) {
#pragma unroll
    for (int kk = 0; kk < 2; ++kk) {
        uint32_t a_hi[4][4], a_lo[4][4], b_hi[2][4], b_lo[2][4];
        const uint32_t arow = (uint32_t)(wm * 64 + (lane & 15));
        const uint32_t acol = ((lane >> 4) * 16) + kk * 32;
#pragma unroll
        for (int mi = 0; mi < 4; ++mi) {
            uint32_t off = (arow + mi * 16) * ROWB + acol;
            ldm_x4(a_hi[mi], sbase + OFF_AH + off);
            ldm_x4(a_lo[mi], sbase + OFF_AL + off);
        }
        const uint32_t brow = (uint32_t)(wn * 32 + ((lane >> 4) << 3) + (lane & 7));
        const uint32_t bcol = (((lane >> 3) & 1) * 16) + kk * 32;
#pragma unroll
        for (int nj = 0; nj < 2; ++nj) {
            uint32_t off = (brow + nj * 16) * ROWB + bcol;
            ldm_x4(b_hi[nj], sbase + offB_h + off);
            ldm_x4(b_lo[nj], sbase + offB_l + off);
        }
#pragma unroll
        for (int mi = 0; mi < 4; ++mi)
#pragma unroll
            for (int nj = 0; nj < 2; ++nj) {
                mma_bf16(acc[mi][nj * 2 + 0], a_hi[mi], &b_hi[nj][0]);
                mma_bf16(acc[mi][nj * 2 + 1], a_hi[mi], &b_hi[nj][2]);
                mma_bf16(acc[mi][nj * 2 + 0], a_hi[mi], &b_lo[nj][0]);
                mma_bf16(acc[mi][nj * 2 + 1], a_hi[mi], &b_lo[nj][2]);
                mma_bf16(acc[mi][nj * 2 + 0], a_lo[mi], &b_hi[nj][0]);
                mma_bf16(acc[mi][nj * 2 + 1], a_lo[mi], &b_hi[nj][2]);
            }
    }
}

// ---------------- syrk: G += x x^T (6 tile-pairs, split-K; diag pairs dedup loads) ----------------
__global__ __launch_bounds__(256) void syrk_mma() {
    extern __shared__ __align__(16) char sm[];
    const int tid = threadIdx.x, lane = tid & 31, wid = tid >> 5;
    const int wm = wid & 1, wn = wid >> 1;
    const int TI[6] = {0, 0, 0, 1, 1, 2};
    const int TJ[6] = {0, 1, 2, 1, 2, 2};
    const int ti = TI[blockIdx.x], tj = TJ[blockIdx.x];
    const bool diag = (ti == tj);
    const int b = blockIdx.z;
    const int kb = blockIdx.y * 1024;

    const __nv_bfloat16* Ah = g_xhi + ((size_t)(b * CDIM + ti * 128)) * HW;
    const __nv_bfloat16* Al = g_xlo + ((size_t)(b * CDIM + ti * 128)) * HW;
    const __nv_bfloat16* Bh = g_xhi + ((size_t)(b * CDIM + tj * 128)) * HW;
    const __nv_bfloat16* Bl = g_xlo + ((size_t)(b * CDIM + tj * 128)) * HW;

    const uint32_t offB_h = diag ? OFF_AH : OFF_BH;
    const uint32_t offB_l = diag ? OFF_AL : OFF_BL;

    float acc[4][4][4];
#pragma unroll
    for (int i = 0; i < 4; ++i)
#pragma unroll
        for (int j = 0; j < 4; ++j)
#pragma unroll
            for (int k = 0; k < 4; ++k) acc[i][j][k] = 0.f;

    const uint32_t sb = smem_u32(sm);
    issue_stage(sb, Ah, Al, Bh, Bl, HW, HW, kb, tid, !diag);
    CP_COMMIT();

    for (int ch = 0; ch < 32; ++ch) {
        CP_WAIT0();
        __syncthreads();
        if (ch < 31) {
            issue_stage(sb + ((ch + 1) & 1) * STAGE_BYTES, Ah, Al, Bh, Bl,
                        HW, HW, kb + (ch + 1) * 32, tid, !diag);
            CP_COMMIT();
        }
        mma_chunk(sb + (ch & 1) * STAGE_BYTES, lane, wm, wn, acc, offB_h, offB_l);
    }

    float* Gp = g_G + (size_t)b * CDIM * CDIM;
    const int r0 = ti * 128 + wm * 64;
    const int c0 = tj * 128 + wn * 32;
#pragma unroll
    for (int mi = 0; mi < 4; ++mi)
#pragma unroll
        for (int f = 0; f < 4; ++f) {
            int row = r0 + mi * 16 + (lane >> 2);
            int col = c0 + f * 8 + (lane & 3) * 2;
            atomicAdd(&Gp[(size_t)row * CDIM + col],           acc[mi][f][0]);
            atomicAdd(&Gp[(size_t)row * CDIM + col + 1],       acc[mi][f][1]);
            atomicAdd(&Gp[(size_t)(row + 8) * CDIM + col],     acc[mi][f][2]);
            atomicAdd(&Gp[(size_t)(row + 8) * CDIM + col + 1], acc[mi][f][3]);
        }
}

// ---------------- wgemm: C = W-split @ B-split, 384x384 per batch ----------------
__global__ __launch_bounds__(256) void wgemm_mma(int mode) {
    extern __shared__ __align__(16) char sm[];
    const int tid = threadIdx.x, lane = tid & 31, wid = tid >> 5;
    const int wm = wid & 1, wn = wid >> 1;
    const int o0 = (blockIdx.x % 3) * 128;
    const int j0 = (blockIdx.x / 3) * 128;
    const int b = blockIdx.y;
    const int which = blockIdx.z;
    const size_t CC = (size_t)CDIM * CDIM;

    const int widx = mode ? 2 : which;
    const __nv_bfloat16* Ah = g_Whi + (size_t)widx * CC + (size_t)o0 * CDIM;
    const __nv_bfloat16* Al = g_Wlo + (size_t)widx * CC + (size_t)o0 * CDIM;
    const __nv_bfloat16* Bh = (mode ? g_BsThi : g_Ghi) + (size_t)b * CC + (size_t)j0 * CDIM;
    const __nv_bfloat16* Bl = (mode ? g_BsTlo : g_Glo) + (size_t)b * CC + (size_t)j0 * CDIM;

    float acc[4][4][4];
#pragma unroll
    for (int i = 0; i < 4; ++i)
#pragma unroll
        for (int j = 0; j < 4; ++j)
#pragma unroll
            for (int k = 0; k < 4; ++k) acc[i][j][k] = 0.f;

    const uint32_t sb = smem_u32(sm);
    issue_stage(sb, Ah, Al, Bh, Bl, CDIM, CDIM, 0, tid, true);
    CP_COMMIT();

    for (int ch = 0; ch < 12; ++ch) {
        CP_WAIT0();
        __syncthreads();
        if (ch < 11) {
            issue_stage(sb + ((ch + 1) & 1) * STAGE_BYTES, Ah, Al, Bh, Bl,
                        CDIM, CDIM, (ch + 1) * 32, tid, true);
            CP_COMMIT();
        }
        mma_chunk(sb + (ch & 1) * STAGE_BYTES, lane, wm, wn, acc, OFF_BH, OFF_BL);
    }

    if (mode == 0) {
        float* C = (which ? g_Rk : g_Rq) + b * CC;
#pragma unroll
        for (int mi = 0; mi < 4; ++mi)
#pragma unroll
            for (int f = 0; f < 4; ++f) {
                int o = o0 + wm * 64 + mi * 16 + (lane >> 2);
                int j = j0 + wn * 32 + f * 8 + (lane & 3) * 2;
                *(float2*)&C[(size_t)o * CDIM + j] =
                    make_float2(acc[mi][f][0], acc[mi][f][1]);
                *(float2*)&C[(size_t)(o + 8) * CDIM + j] =
                    make_float2(acc[mi][f][2], acc[mi][f][3]);
            }
    } else {
#pragma unroll
        for (int mi = 0; mi < 4; ++mi)
#pragma unroll
            for (int f = 0; f < 4; ++f) {
                int o = o0 + wm * 64 + mi * 16 + (lane >> 2);
                int j = j0 + wn * 32 + f * 8 + (lane & 3) * 2;
#pragma unroll
                for (int half = 0; half < 2; ++half) {
                    float v0 = acc[mi][f][half * 2 + 0];
                    float v1 = acc[mi][f][half * 2 + 1];
                    __nv_bfloat16 h0 = __float2bfloat16(v0);
                    __nv_bfloat16 h1 = __float2bfloat16(v1);
                    __nv_bfloat16 l0 = __float2bfloat16(v0 - __bfloat162float(h0));
                    __nv_bfloat16 l1 = __float2bfloat16(v1 - __bfloat162float(h1));
                    size_t off = b * CC + (size_t)(o + half * 8) * CDIM + j;
                    *(__nv_bfloat162*)(g_Mhi + off) = __nv_bfloat162(h0, h1);
                    *(__nv_bfloat162*)(g_Mlo + off) = __nv_bfloat162(l0, l1);
                }
            }
    }
}

// ---------------- out = M @ x: B read from PLAIN x via ldmatrix.trans ----------------
#define O_BROWB 272
#define O_AH 0
#define O_AL 10240
#define O_BH 20480
#define O_BL (20480 + 32 * O_BROWB)     // 29184
#define O_STAGE (O_BL + 32 * O_BROWB)   // 37888
#define OUT_SMEM (2 * O_STAGE)          // 75776

__global__ __launch_bounds__(256) void out_mma(float* __restrict__ out) {
    extern __shared__ __align__(16) char sm[];
    const int tid = threadIdx.x, lane = tid & 31, wid = tid >> 5;
    const int wm = wid & 1, wn = wid >> 1;
    const int ntile = blockIdx.x;
    const int otile = blockIdx.y;
    const int b = blockIdx.z;
    const size_t CC = (size_t)CDIM * CDIM;

    const __nv_bfloat16* Ah = g_Mhi + (size_t)b * CC + (size_t)(otile * 128) * CDIM;
    const __nv_bfloat16* Al = g_Mlo + (size_t)b * CC + (size_t)(otile * 128) * CDIM;
    const __nv_bfloat16* Xh = g_xhi + (size_t)b * CDIM * HW + (size_t)ntile * 128;
    const __nv_bfloat16* Xl = g_xlo + (size_t)b * CDIM * HW + (size_t)ntile * 128;

    float acc[4][4][4];
#pragma unroll
    for (int i = 0; i < 4; ++i)
#pragma unroll
        for (int j = 0; j < 4; ++j)
#pragma unroll
            for (int k = 0; k < 4; ++k) acc[i][j][k] = 0.f;

    const uint32_t sb = smem_u32(sm);

    auto issue = [&](uint32_t sdst, int cbase) {
#pragma unroll
        for (int t = 0; t < 2; ++t) {
            int idx = t * 256 + tid;
            {   // A: M tile 128o x 32c
                int r = idx >> 2, g = idx & 3;
                uint32_t so = (uint32_t)(r * ROWB + g * 16);
                size_t go = (size_t)r * CDIM + cbase + g * 8;
                cp_async16(sdst + O_AH + so, Ah + go);
                cp_async16(sdst + O_AL + so, Al + go);
            }
            {   // B: x tile 32c x 128n
                int r = idx >> 4, c16 = idx & 15;
                uint32_t so = (uint32_t)(r * O_BROWB + c16 * 16);
                size_t go = (size_t)(cbase + r) * HW + c16 * 8;
                cp_async16(sdst + O_BH + so, Xh + go);
                cp_async16(sdst + O_BL + so, Xl + go);
            }
        }
    };

    issue(sb, 0);
    CP_COMMIT();

    for (int ch = 0; ch < 12; ++ch) {
        CP_WAIT0();
        __syncthreads();
        if (ch < 11) {
            issue(sb + ((ch + 1) & 1) * O_STAGE, (ch + 1) * 32);
            CP_COMMIT();
        }
        const uint32_t sbase = sb + (ch & 1) * O_STAGE;
#pragma unroll
        for (int kk = 0; kk < 2; ++kk) {
            uint32_t a_hi[4][4], a_lo[4][4], b_hi[2][4], b_lo[2][4];
            const uint32_t arow = (uint32_t)(wm * 64 + (lane & 15));
            const uint32_t acol = ((lane >> 4) * 16) + kk * 32;
#pragma unroll
            for (int mi = 0; mi < 4; ++mi) {
                uint32_t off = (arow + mi * 16) * ROWB + acol;
                ldm_x4(a_hi[mi], sbase + O_AH + off);
                ldm_x4(a_lo[mi], sbase + O_AL + off);
            }
            const uint32_t brow = (uint32_t)(kk * 16 + (lane & 7) + ((lane >> 3) & 1) * 8);
#pragma unroll
            for (int nj = 0; nj < 2; ++nj) {
                uint32_t bcol = (uint32_t)(wn * 32 + nj * 16 + (lane >> 4) * 8) * 2;
                uint32_t off = brow * O_BROWB + bcol;
                ldm_x4_trans(b_hi[nj], sbase + O_BH + off);
                ldm_x4_trans(b_lo[nj], sbase + O_BL + off);
            }
#pragma unroll
            for (int mi = 0; mi < 4; ++mi)
#pragma unroll
                for (int nj = 0; nj < 2; ++nj) {
                    mma_bf16(acc[mi][nj * 2 + 0], a_hi[mi], &b_hi[nj][0]);
                    mma_bf16(acc[mi][nj * 2 + 1], a_hi[mi], &b_hi[nj][2]);
                    mma_bf16(acc[mi][nj * 2 + 0], a_hi[mi], &b_lo[nj][0]);
                    mma_bf16(acc[mi][nj * 2 + 1], a_hi[mi], &b_lo[nj][2]);
                    mma_bf16(acc[mi][nj * 2 + 0], a_lo[mi], &b_hi[nj][0]);
                    mma_bf16(acc[mi][nj * 2 + 1], a_lo[mi], &b_hi[nj][2]);
                }
        }
    }

    const int o0 = otile * 128 + wm * 64;
    const int n0 = ntile * 128 + wn * 32;
#pragma unroll
    for (int mi = 0; mi < 4; ++mi)
#pragma unroll
        for (int f = 0; f < 4; ++f) {
            int o = o0 + mi * 16 + (lane >> 2);
            int n = n0 + f * 8 + (lane & 3) * 2;
            *(float2*)&out[((size_t)b * CDIM + o) * HW + n] =
                make_float2(acc[mi][f][0], acc[mi][f][1]);
            *(float2*)&out[((size_t)b * CDIM + o + 8) * HW + n] =
                make_float2(acc[mi][f][2], acc[mi][f][3]);
        }
}

// ---------------- fp32 SIMT tail ----------------
__global__ void norms_kernel(const float* __restrict__ wq, const float* __restrict__ wk) {
    const int which = blockIdx.x;
    const int b = blockIdx.y;
    const float* R = (which ? g_Rk : g_Rq) + (size_t)b * CDIM * CDIM;
    const float* W = which ? wk : wq;
    float* inv = (which ? g_invk : g_invq) + b * CDIM;
    const int lane = threadIdx.x & 31;
    const int wd = threadIdx.x >> 5;
    for (int r = wd; r < CDIM; r += 12) {
        float s = 0.f;
        for (int j = lane; j < CDIM; j += 32)
            s = fmaf(R[(size_t)r * CDIM + j], W[(size_t)r * CDIM + j], s);
#pragma unroll
        for (int o = 16; o; o >>= 1) s += __shfl_xor_sync(0xffffffffu, s, o);
        if (lane == 0) inv[r] = 1.f / fmaxf(sqrtf(fmaxf(s, 0.f)), EPS);
    }
}

__global__ __launch_bounds__(256) void s_kernel(const float* __restrict__ wk) {
    const int bh = blockIdx.x;
    const int b = bh >> 3;
    const int h = bh & 7;
    const int tid = threadIdx.x;

    __shared__ float qs[CH][68];
    __shared__ float ks[CH][68];

    const int c0 = (tid >> 4) * 3;
    const int d0 = (tid & 15) * 3;

    float acc[3][3];
#pragma unroll
    for (int i = 0; i < 3; ++i)
#pragma unroll
        for (int j = 0; j < 3; ++j) acc[i][j] = 0.f;

    const float* Rq = g_Rq + (size_t)b * CDIM * CDIM + (size_t)(h * CH) * CDIM;
    const float* Wk = wk + (size_t)(h * CH) * CDIM;

    for (int ck = 0; ck < 6; ++ck) {
        const int koff = ck * 64;
#pragma unroll
        for (int t = 0; t < 3; ++t) {
            int idx = t * 256 + tid;
            int row = idx >> 4;
            int col = (idx & 15) * 4;
            *(float4*)&qs[row][col] = *(const float4*)(Rq + (size_t)row * CDIM + koff + col);
            *(float4*)&ks[row][col] = *(const float4*)(Wk + (size_t)row * CDIM + koff + col);
        }
        __syncthreads();
#pragma unroll 8
        for (int kk = 0; kk < 64; ++kk) {
            float q0 = qs[c0 + 0][kk], q1 = qs[c0 + 1][kk], q2 = qs[c0 + 2][kk];
            float k0 = ks[d0 + 0][kk], k1 = ks[d0 + 1][kk], k2 = ks[d0 + 2][kk];
            acc[0][0] = fmaf(q0, k0, acc[0][0]);
            acc[0][1] = fmaf(q0, k1, acc[0][1]);
            acc[0][2] = fmaf(q0, k2, acc[0][2]);
            acc[1][0] = fmaf(q1, k0, acc[1][0]);
            acc[1][1] = fmaf(q1, k1, acc[1][1]);
            acc[1][2] = fmaf(q1, k2, acc[1][2]);
            acc[2][0] = fmaf(q2, k0, acc[2][0]);
            acc[2][1] = fmaf(q2, k1, acc[2][1]);
            acc[2][2] = fmaf(q2, k2, acc[2][2]);
        }
        __syncthreads();
    }

    float* Sb = g_S + (size_t)bh * CH * CH;
#pragma unroll
    for (int i = 0; i < 3; ++i)
#pragma unroll
        for (int j = 0; j < 3; ++j)
            Sb[(c0 + i) * CH + (d0 + j)] = acc[i][j];
}

__global__ void attn_softmax_kernel(const float* __restrict__ temperature) {
    const int bh = blockIdx.x;
    const int b = bh >> 3;
    const int h = bh & 7;
    const int c = threadIdx.x;
    if (c >= CH) return;

    const float t = temperature[h];
    const float sq = g_invq[b * CDIM + h * CH + c] * t;
    const float* Srow = g_S + (size_t)bh * CH * CH + c * CH;
    const float* ik = g_invk + b * CDIM + h * CH;

    float v[CH];
    float m = -1e30f;
#pragma unroll
    for (int d = 0; d < CH; ++d) {
        v[d] = Srow[d] * sq * ik[d];
        m = fmaxf(m, v[d]);
    }
    float sum = 0.f;
#pragma unroll
    for (int d = 0; d < CH; ++d) {
        v[d] = __expf(v[d] - m);
        sum += v[d];
    }
    float inv = 1.f / sum;
    float* Arow = g_A + (size_t)bh * CH * CH + c * CH;
#pragma unroll
    for (int d = 0; d < CH; ++d) Arow[d] = v[d] * inv;
}

__global__ __launch_bounds__(384) void bstack_T(const float* __restrict__ wv) {
    const int bh = blockIdx.x;
    const int b = bh >> 3;
    const int h = bh & 7;

    __shared__ float As[CH * CH];
    const float* Ahp = g_A + (size_t)bh * CH * CH;
    for (int i = threadIdx.x; i < CH * CH; i += 384) As[i] = Ahp[i];
    __syncthreads();

    const int m = threadIdx.x;
    float acc[CH];
#pragma unroll
    for (int i = 0; i < CH; ++i) acc[i] = 0.f;

    const float* wvp = wv + (size_t)(h * CH) * CDIM + m;
    for (int d = 0; d < CH; ++d) {
        float wvv = wvp[(size_t)d * CDIM];
#pragma unroll
        for (int cp = 0; cp < CH; ++cp) acc[cp] = fmaf(As[cp * CH + d], wvv, acc[cp]);
    }
    size_t base = ((size_t)b * CDIM + m) * CDIM + h * CH;
    __align__(16) __nv_bfloat16 hh[CH], ll[CH];
#pragma unroll
    for (int cp = 0; cp < CH; ++cp) {
        __nv_bfloat16 hv = __float2bfloat16(acc[cp]);
        hh[cp] = hv;
        ll[cp] = __float2bfloat16(acc[cp] - __bfloat162float(hv));
    }
#pragma unroll
    for (int q = 0; q < CH / 4; ++q) {
        *(uint2*)(g_BsThi + base + q * 4) = *(const uint2*)(hh + q * 4);
        *(uint2*)(g_BsTlo + base + q * 4) = *(const uint2*)(ll + q * 4);
    }
}

// ---------------- launcher ----------------
extern "C" void kernel_launch(void* const* d_in, const int* in_sizes, int n_in,
                              void* d_out, int out_size) {
    const float* x    = (const float*)d_in[0];
    const float* wq   = (const float*)d_in[1];
    const float* wk   = (const float*)d_in[2];
    const float* wv   = (const float*)d_in[3];
    const float* wo   = (const float*)d_in[4];
    const float* temp = (const float*)d_in[5];
    float* out = (float*)d_out;

    cudaFuncSetAttribute(syrk_mma, cudaFuncAttributeMaxDynamicSharedMemorySize, PIPE_SMEM);
    cudaFuncSetAttribute(wgemm_mma, cudaFuncAttributeMaxDynamicSharedMemorySize, PIPE_SMEM);
    cudaFuncSetAttribute(out_mma, cudaFuncAttributeMaxDynamicSharedMemorySize, OUT_SMEM);

    const size_t CC = (size_t)CDIM * CDIM;
    const int nG = (int)(((size_t)BATCH * CC + 255) / 256);

    convert_plain<<<24576, 256>>>(x);
    convert_W<<<(CDIM * CDIM + 255) / 256, 256>>>(wq, wk, wo);
    zero_G_kernel<<<nG, 256>>>();
    syrk_mma<<<dim3(6, 16, BATCH), 256, PIPE_SMEM>>>();
    mirror_convert_G<<<nG, 256>>>();

    wgemm_mma<<<dim3(9, BATCH, 2), 256, PIPE_SMEM>>>(0);   // Rq, Rk

    norms_kernel<<<dim3(2, BATCH), 384>>>(wq, wk);
    s_kernel<<<BATCH * NHEAD, 256>>>(wk);
    attn_softmax_kernel<<<BATCH * NHEAD, 64>>>(temp);
    bstack_T<<<BATCH * NHEAD, 384>>>(wv);

    wgemm_mma<<<dim3(9, BATCH, 1), 256, PIPE_SMEM>>>(1);   // Mhi/Mlo

    out_mma<<<dim3(HW / 128, 3, BATCH), 256, OUT_SMEM>>>(out);
}

// round 13
// speedup vs baseline: 1.0858x; 1.0019x over previous
#include <cuda_runtime.h>
#include <cuda_bf16.h>
#include <math.h>
#include <stdint.h>

#define BATCH 8
#define CDIM 384
#define NHEAD 8
#define CH 48
#define HW 16384
#define EPS 1e-12f

// ---------------- warp-MMA + cp.async helpers (plain sm_80+ PTX) ----------------
__device__ __forceinline__ uint32_t smem_u32(const void* p) {
    uint32_t a;
    asm("{ .reg .u64 t; cvta.to.shared.u64 t, %1; cvt.u32.u64 %0, t; }" : "=r"(a) : "l"(p));
    return a;
}
__device__ __forceinline__ void ldm_x4(uint32_t* r, uint32_t addr) {
    asm volatile("ldmatrix.sync.aligned.m8n8.x4.shared.b16 {%0,%1,%2,%3}, [%4];"
                 : "=r"(r[0]), "=r"(r[1]), "=r"(r[2]), "=r"(r[3]) : "r"(addr));
}
__device__ __forceinline__ void ldm_x4_trans(uint32_t* r, uint32_t addr) {
    asm volatile("ldmatrix.sync.aligned.m8n8.x4.trans.shared.b16 {%0,%1,%2,%3}, [%4];"
                 : "=r"(r[0]), "=r"(r[1]), "=r"(r[2]), "=r"(r[3]) : "r"(addr));
}
__device__ __forceinline__ void mma_bf16(float* d, const uint32_t* a, const uint32_t* b) {
    asm volatile(
        "mma.sync.aligned.m16n8k16.row.col.f32.bf16.bf16.f32 "
        "{%0,%1,%2,%3}, {%4,%5,%6,%7}, {%8,%9}, {%0,%1,%2,%3};"
        : "+f"(d[0]), "+f"(d[1]), "+f"(d[2]), "+f"(d[3])
        : "r"(a[0]), "r"(a[1]), "r"(a[2]), "r"(a[3]), "r"(b[0]), "r"(b[1]));
}
__device__ __forceinline__ void cp_async16(uint32_t saddr, const void* gptr) {
    asm volatile("cp.async.cg.shared.global [%0], [%1], 16;" :: "r"(saddr), "l"(gptr));
}
#define CP_COMMIT() asm volatile("cp.async.commit_group;")
#define CP_WAIT0()  asm volatile("cp.async.wait_group 0;")

// ---------------- scratch ----------------
__device__ float g_G [(size_t)BATCH * CDIM * CDIM];
__device__ float g_Rq[(size_t)BATCH * CDIM * CDIM];
__device__ float g_Rk[(size_t)BATCH * CDIM * CDIM];
__device__ float g_invq[BATCH * CDIM];
__device__ float g_invk[BATCH * CDIM];
__device__ float g_S [BATCH * NHEAD * CH * CH];
__device__ float g_A [BATCH * NHEAD * CH * CH];

__device__ __nv_bfloat16 g_xhi [(size_t)BATCH * CDIM * HW];   // [b][c][n]
__device__ __nv_bfloat16 g_xlo [(size_t)BATCH * CDIM * HW];
__device__ __nv_bfloat16 g_Ghi [(size_t)BATCH * CDIM * CDIM];
__device__ __nv_bfloat16 g_Glo [(size_t)BATCH * CDIM * CDIM];
__device__ __nv_bfloat16 g_BsThi[(size_t)BATCH * CDIM * CDIM]; // [b][m][c]
__device__ __nv_bfloat16 g_BsTlo[(size_t)BATCH * CDIM * CDIM];
__device__ __nv_bfloat16 g_Mhi [(size_t)BATCH * CDIM * CDIM];
__device__ __nv_bfloat16 g_Mlo [(size_t)BATCH * CDIM * CDIM];
__device__ __nv_bfloat16 g_Whi [3 * CDIM * CDIM];
__device__ __nv_bfloat16 g_Wlo [3 * CDIM * CDIM];

// ---------------- converts ----------------
__global__ void convert_plain(const float* __restrict__ x) {
    size_t i = ((size_t)blockIdx.x * 256 + threadIdx.x) * 8;
    float4 v0 = *(const float4*)(x + i);
    float4 v1 = *(const float4*)(x + i + 4);
    float v[8] = {v0.x, v0.y, v0.z, v0.w, v1.x, v1.y, v1.z, v1.w};
    __align__(16) __nv_bfloat16 hh[8], ll[8];
#pragma unroll
    for (int j = 0; j < 8; ++j) {
        __nv_bfloat16 h = __float2bfloat16(v[j]);
        hh[j] = h;
        ll[j] = __float2bfloat16(v[j] - __bfloat162float(h));
    }
    *(uint4*)(g_xhi + i) = *(const uint4*)hh;
    *(uint4*)(g_xlo + i) = *(const uint4*)ll;
}

__global__ void convert_W(const float* __restrict__ wq, const float* __restrict__ wk,
                          const float* __restrict__ wo) {
    int i = blockIdx.x * 256 + threadIdx.x;
    if (i >= CDIM * CDIM) return;
    const float* srcs[3] = {wq, wk, wo};
#pragma unroll
    for (int m = 0; m < 3; ++m) {
        float v = srcs[m][i];
        __nv_bfloat16 h = __float2bfloat16(v);
        g_Whi[m * CDIM * CDIM + i] = h;
        g_Wlo[m * CDIM * CDIM + i] = __float2bfloat16(v - __bfloat162float(h));
    }
}

__global__ void zero_G_kernel() {
    size_t i = (size_t)blockIdx.x * 256 + threadIdx.x;
    if (i < (size_t)BATCH * CDIM * CDIM) g_G[i] = 0.f;
}

__global__ void mirror_convert_G() {
    size_t i = (size_t)blockIdx.x * 256 + threadIdx.x;
    if (i >= (size_t)BATCH * CDIM * CDIM) return;
    size_t bb = i / (CDIM * CDIM);
    int rc = (int)(i % (CDIM * CDIM));
    int r = rc / CDIM, c = rc % CDIM;
    float v;
    if ((r >> 7) > (c >> 7)) {
        v = g_G[bb * CDIM * CDIM + (size_t)c * CDIM + r];
        g_G[i] = v;
    } else {
        v = g_G[i];
    }
    __nv_bfloat16 h = __float2bfloat16(v);
    g_Ghi[i] = h;
    g_Glo[i] = __float2bfloat16(v - __bfloat162float(h));
}

// ---------------- MMA tile geometry ----------------
#define ROWB 80
#define TILE_BYTES (128 * ROWB)
#define OFF_AH 0
#define OFF_AL (1 * TILE_BYTES)
#define OFF_BH (2 * TILE_BYTES)
#define OFF_BL (3 * TILE_BYTES)
#define STAGE_BYTES (4 * TILE_BYTES)   // 40960
#define PIPE_SMEM (2 * STAGE_BYTES)    // 81920

__device__ __forceinline__ void issue_stage(uint32_t sdst,
    const __nv_bfloat16* Ah, const __nv_bfloat16* Al,
    const __nv_bfloat16* Bh, const __nv_bfloat16* Bl,
    size_t strideA, size_t strideB, int k0, int tid, bool loadB)
{
#pragma unroll
    for (int t = 0; t < 2; ++t) {
        int idx = t * 256 + tid;
        int r = idx >> 2, g = idx & 3;
        uint32_t so = (uint32_t)(r * ROWB + g * 16);
        size_t goA = (size_t)r * strideA + k0 + g * 8;
        cp_async16(sdst + OFF_AH + so, Ah + goA);
        cp_async16(sdst + OFF_AL + so, Al + goA);
        if (loadB) {
            size_t goB = (size_t)r * strideB + k0 + g * 8;
            cp_async16(sdst + OFF_BH + so, Bh + goB);
            cp_async16(sdst + OFF_BL + so, Bl + goB);
        }
    }
}

// Term-major MMA: consecutive HMMAs target distinct accumulators (RAW chain
// reuse distance 16 instead of 1). Per-accumulator add order unchanged:
// each acc receives hh, then hl, then lh — bit-identical to the pair-major order.
__device__ __forceinline__ void mma_chunk(uint32_t sbase, int lane, int wm, int wn,
                                          float acc[4][4][4],
                                          uint32_t offB_h, uint32_t offB_l) {
#pragma unroll
    for (int kk = 0; kk < 2; ++kk) {
        uint32_t a_hi[4][4], a_lo[4][4], b_hi[2][4], b_lo[2][4];
        const uint32_t arow = (uint32_t)(wm * 64 + (lane & 15));
        const uint32_t acol = ((lane >> 4) * 16) + kk * 32;
#pragma unroll
        for (int mi = 0; mi < 4; ++mi) {
            uint32_t off = (arow + mi * 16) * ROWB + acol;
            ldm_x4(a_hi[mi], sbase + OFF_AH + off);
            ldm_x4(a_lo[mi], sbase + OFF_AL + off);
        }
        const uint32_t brow = (uint32_t)(wn * 32 + ((lane >> 4) << 3) + (lane & 7));
        const uint32_t bcol = (((lane >> 3) & 1) * 16) + kk * 32;
#pragma unroll
        for (int nj = 0; nj < 2; ++nj) {
            uint32_t off = (brow + nj * 16) * ROWB + bcol;
            ldm_x4(b_hi[nj], sbase + offB_h + off);
            ldm_x4(b_lo[nj], sbase + offB_l + off);
        }
#pragma unroll
        for (int t = 0; t < 3; ++t) {
            const uint32_t (*ap)[4] = (t == 2) ? a_lo : a_hi;
            const uint32_t (*bp)[4] = (t == 1) ? b_lo : b_hi;
#pragma unroll
            for (int mi = 0; mi < 4; ++mi)
#pragma unroll
                for (int nj = 0; nj < 2; ++nj) {
                    mma_bf16(acc[mi][nj * 2 + 0], ap[mi], &bp[nj][0]);
                    mma_bf16(acc[mi][nj * 2 + 1], ap[mi], &bp[nj][2]);
                }
        }
    }
}

// ---------------- syrk: G += x x^T (6 tile-pairs, split-K; diag dedup) ----------------
__global__ __launch_bounds__(256) void syrk_mma() {
    extern __shared__ __align__(16) char sm[];
    const int tid = threadIdx.x, lane = tid & 31, wid = tid >> 5;
    const int wm = wid & 1, wn = wid >> 1;
    const int TI[6] = {0, 0, 0, 1, 1, 2};
    const int TJ[6] = {0, 1, 2, 1, 2, 2};
    const int ti = TI[blockIdx.x], tj = TJ[blockIdx.x];
    const bool diag = (ti == tj);
    const int b = blockIdx.z;
    const int kb = blockIdx.y * 1024;

    const __nv_bfloat16* Ah = g_xhi + ((size_t)(b * CDIM + ti * 128)) * HW;
    const __nv_bfloat16* Al = g_xlo + ((size_t)(b * CDIM + ti * 128)) * HW;
    const __nv_bfloat16* Bh = g_xhi + ((size_t)(b * CDIM + tj * 128)) * HW;
    const __nv_bfloat16* Bl = g_xlo + ((size_t)(b * CDIM + tj * 128)) * HW;

    const uint32_t offB_h = diag ? OFF_AH : OFF_BH;
    const uint32_t offB_l = diag ? OFF_AL : OFF_BL;

    float acc[4][4][4];
#pragma unroll
    for (int i = 0; i < 4; ++i)
#pragma unroll
        for (int j = 0; j < 4; ++j)
#pragma unroll
            for (int k = 0; k < 4; ++k) acc[i][j][k] = 0.f;

    const uint32_t sb = smem_u32(sm);
    issue_stage(sb, Ah, Al, Bh, Bl, HW, HW, kb, tid, !diag);
    CP_COMMIT();

    for (int ch = 0; ch < 32; ++ch) {
        CP_WAIT0();
        __syncthreads();
        if (ch < 31) {
            issue_stage(sb + ((ch + 1) & 1) * STAGE_BYTES, Ah, Al, Bh, Bl,
                        HW, HW, kb + (ch + 1) * 32, tid, !diag);
            CP_COMMIT();
        }
        mma_chunk(sb + (ch & 1) * STAGE_BYTES, lane, wm, wn, acc, offB_h, offB_l);
    }

    float* Gp = g_G + (size_t)b * CDIM * CDIM;
    const int r0 = ti * 128 + wm * 64;
    const int c0 = tj * 128 + wn * 32;
#pragma unroll
    for (int mi = 0; mi < 4; ++mi)
#pragma unroll
        for (int f = 0; f < 4; ++f) {
            int row = r0 + mi * 16 + (lane >> 2);
            int col = c0 + f * 8 + (lane & 3) * 2;
            atomicAdd(&Gp[(size_t)row * CDIM + col],           acc[mi][f][0]);
            atomicAdd(&Gp[(size_t)row * CDIM + col + 1],       acc[mi][f][1]);
            atomicAdd(&Gp[(size_t)(row + 8) * CDIM + col],     acc[mi][f][2]);
            atomicAdd(&Gp[(size_t)(row + 8) * CDIM + col + 1], acc[mi][f][3]);
        }
}

// ---------------- wgemm: C = W-split @ B-split, 384x384 per batch ----------------
__global__ __launch_bounds__(256) void wgemm_mma(int mode) {
    extern __shared__ __align__(16) char sm[];
    const int tid = threadIdx.x, lane = tid & 31, wid = tid >> 5;
    const int wm = wid & 1, wn = wid >> 1;
    const int o0 = (blockIdx.x % 3) * 128;
    const int j0 = (blockIdx.x / 3) * 128;
    const int b = blockIdx.y;
    const int which = blockIdx.z;
    const size_t CC = (size_t)CDIM * CDIM;

    const int widx = mode ? 2 : which;
    const __nv_bfloat16* Ah = g_Whi + (size_t)widx * CC + (size_t)o0 * CDIM;
    const __nv_bfloat16* Al = g_Wlo + (size_t)widx * CC + (size_t)o0 * CDIM;
    const __nv_bfloat16* Bh = (mode ? g_BsThi : g_Ghi) + (size_t)b * CC + (size_t)j0 * CDIM;
    const __nv_bfloat16* Bl = (mode ? g_BsTlo : g_Glo) + (size_t)b * CC + (size_t)j0 * CDIM;

    float acc[4][4][4];
#pragma unroll
    for (int i = 0; i < 4; ++i)
#pragma unroll
        for (int j = 0; j < 4; ++j)
#pragma unroll
            for (int k = 0; k < 4; ++k) acc[i][j][k] = 0.f;

    const uint32_t sb = smem_u32(sm);
    issue_stage(sb, Ah, Al, Bh, Bl, CDIM, CDIM, 0, tid, true);
    CP_COMMIT();

    for (int ch = 0; ch < 12; ++ch) {
        CP_WAIT0();
        __syncthreads();
        if (ch < 11) {
            issue_stage(sb + ((ch + 1) & 1) * STAGE_BYTES, Ah, Al, Bh, Bl,
                        CDIM, CDIM, (ch + 1) * 32, tid, true);
            CP_COMMIT();
        }
        mma_chunk(sb + (ch & 1) * STAGE_BYTES, lane, wm, wn, acc, OFF_BH, OFF_BL);
    }

    if (mode == 0) {
        float* C = (which ? g_Rk : g_Rq) + b * CC;
#pragma unroll
        for (int mi = 0; mi < 4; ++mi)
#pragma unroll
            for (int f = 0; f < 4; ++f) {
                int o = o0 + wm * 64 + mi * 16 + (lane >> 2);
                int j = j0 + wn * 32 + f * 8 + (lane & 3) * 2;
                *(float2*)&C[(size_t)o * CDIM + j] =
                    make_float2(acc[mi][f][0], acc[mi][f][1]);
                *(float2*)&C[(size_t)(o + 8) * CDIM + j] =
                    make_float2(acc[mi][f][2], acc[mi][f][3]);
            }
    } else {
#pragma unroll
        for (int mi = 0; mi < 4; ++mi)
#pragma unroll
            for (int f = 0; f < 4; ++f) {
                int o = o0 + wm * 64 + mi * 16 + (lane >> 2);
                int j = j0 + wn * 32 + f * 8 + (lane & 3) * 2;
#pragma unroll
                for (int half = 0; half < 2; ++half) {
                    float v0 = acc[mi][f][half * 2 + 0];
                    float v1 = acc[mi][f][half * 2 + 1];
                    __nv_bfloat16 h0 = __float2bfloat16(v0);
                    __nv_bfloat16 h1 = __float2bfloat16(v1);
                    __nv_bfloat16 l0 = __float2bfloat16(v0 - __bfloat162float(h0));
                    __nv_bfloat16 l1 = __float2bfloat16(v1 - __bfloat162float(h1));
                    size_t off = b * CC + (size_t)(o + half * 8) * CDIM + j;
                    *(__nv_bfloat162*)(g_Mhi + off) = __nv_bfloat162(h0, h1);
                    *(__nv_bfloat162*)(g_Mlo + off) = __nv_bfloat162(l0, l1);
                }
            }
    }
}

// ---------------- out = M @ x: B read from PLAIN x via ldmatrix.trans ----------------
#define O_BROWB 272
#define O_AH 0
#define O_AL 10240
#define O_BH 20480
#define O_BL (20480 + 32 * O_BROWB)     // 29184
#define O_STAGE (O_BL + 32 * O_BROWB)   // 37888
#define OUT_SMEM (2 * O_STAGE)          // 75776

__global__ __launch_bounds__(256) void out_mma(float* __restrict__ out) {
    extern __shared__ __align__(16) char sm[];
    const int tid = threadIdx.x, lane = tid & 31, wid = tid >> 5;
    const int wm = wid & 1, wn = wid >> 1;
    const int ntile = blockIdx.x;
    const int otile = blockIdx.y;
    const int b = blockIdx.z;
    const size_t CC = (size_t)CDIM * CDIM;

    const __nv_bfloat16* Ah = g_Mhi + (size_t)b * CC + (size_t)(otile * 128) * CDIM;
    const __nv_bfloat16* Al = g_Mlo + (size_t)b * CC + (size_t)(otile * 128) * CDIM;
    const __nv_bfloat16* Xh = g_xhi + (size_t)b * CDIM * HW + (size_t)ntile * 128;
    const __nv_bfloat16* Xl = g_xlo + (size_t)b * CDIM * HW + (size_t)ntile * 128;

    float acc[4][4][4];
#pragma unroll
    for (int i = 0; i < 4; ++i)
#pragma unroll
        for (int j = 0; j < 4; ++j)
#pragma unroll
            for (int k = 0; k < 4; ++k) acc[i][j][k] = 0.f;

    const uint32_t sb = smem_u32(sm);

    auto issue = [&](uint32_t sdst, int cbase) {
#pragma unroll
        for (int t = 0; t < 2; ++t) {
            int idx = t * 256 + tid;
            {   // A: M tile 128o x 32c
                int r = idx >> 2, g = idx & 3;
                uint32_t so = (uint32_t)(r * ROWB + g * 16);
                size_t go = (size_t)r * CDIM + cbase + g * 8;
                cp_async16(sdst + O_AH + so, Ah + go);
                cp_async16(sdst + O_AL + so, Al + go);
            }
            {   // B: x tile 32c x 128n
                int r = idx >> 4, c16 = idx & 15;
                uint32_t so = (uint32_t)(r * O_BROWB + c16 * 16);
                size_t go = (size_t)(cbase + r) * HW + c16 * 8;
                cp_async16(sdst + O_BH + so, Xh + go);
                cp_async16(sdst + O_BL + so, Xl + go);
            }
        }
    };

    issue(sb, 0);
    CP_COMMIT();

    for (int ch = 0; ch < 12; ++ch) {
        CP_WAIT0();
        __syncthreads();
        if (ch < 11) {
            issue(sb + ((ch + 1) & 1) * O_STAGE, (ch + 1) * 32);
            CP_COMMIT();
        }
        const uint32_t sbase = sb + (ch & 1) * O_STAGE;
#pragma unroll
        for (int kk = 0; kk < 2; ++kk) {
            uint32_t a_hi[4][4], a_lo[4][4], b_hi[2][4], b_lo[2][4];
            const uint32_t arow = (uint32_t)(wm * 64 + (lane & 15));
            const uint32_t acol = ((lane >> 4) * 16) + kk * 32;
#pragma unroll
            for (int mi = 0; mi < 4; ++mi) {
                uint32_t off = (arow + mi * 16) * ROWB + acol;
                ldm_x4(a_hi[mi], sbase + O_AH + off);
                ldm_x4(a_lo[mi], sbase + O_AL + off);
            }
            const uint32_t brow = (uint32_t)(kk * 16 + (lane & 7) + ((lane >> 3) & 1) * 8);
#pragma unroll
            for (int nj = 0; nj < 2; ++nj) {
                uint32_t bcol = (uint32_t)(wn * 32 + nj * 16 + (lane >> 4) * 8) * 2;
                uint32_t off = brow * O_BROWB + bcol;
                ldm_x4_trans(b_hi[nj], sbase + O_BH + off);
                ldm_x4_trans(b_lo[nj], sbase + O_BL + off);
            }
            // term-major: distinct accumulators back-to-back; per-acc order hh,hl,lh
#pragma unroll
            for (int t = 0; t < 3; ++t) {
                const uint32_t (*ap)[4] = (t == 2) ? a_lo : a_hi;
                const uint32_t (*bp)[4] = (t == 1) ? b_lo : b_hi;
#pragma unroll
                for (int mi = 0; mi < 4; ++mi)
#pragma unroll
                    for (int nj = 0; nj < 2; ++nj) {
                        mma_bf16(acc[mi][nj * 2 + 0], ap[mi], &bp[nj][0]);
                        mma_bf16(acc[mi][nj * 2 + 1], ap[mi], &bp[nj][2]);
                    }
            }
        }
    }

    const int o0 = otile * 128 + wm * 64;
    const int n0 = ntile * 128 + wn * 32;
#pragma unroll
    for (int mi = 0; mi < 4; ++mi)
#pragma unroll
        for (int f = 0; f < 4; ++f) {
            int o = o0 + mi * 16 + (lane >> 2);
            int n = n0 + f * 8 + (lane & 3) * 2;
            *(float2*)&out[((size_t)b * CDIM + o) * HW + n] =
                make_float2(acc[mi][f][0], acc[mi][f][1]);
            *(float2*)&out[((size_t)b * CDIM + o + 8) * HW + n] =
                make_float2(acc[mi][f][2], acc[mi][f][3]);
        }
}

// ---------------- fp32 SIMT tail ----------------
__global__ void norms_kernel(const float* __restrict__ wq, const float* __restrict__ wk) {
    const int which = blockIdx.x;
    const int b = blockIdx.y;
    const float* R = (which ? g_Rk : g_Rq) + (size_t)b * CDIM * CDIM;
    const float* W = which ? wk : wq;
    float* inv = (which ? g_invk : g_invq) + b * CDIM;
    const int lane = threadIdx.x & 31;
    const int wd = threadIdx.x >> 5;
    for (int r = wd; r < CDIM; r += 12) {
        float s = 0.f;
        for (int j = lane; j < CDIM; j += 32)
            s = fmaf(R[(size_t)r * CDIM + j], W[(size_t)r * CDIM + j], s);
#pragma unroll
        for (int o = 16; o; o >>= 1) s += __shfl_xor_sync(0xffffffffu, s, o);
        if (lane == 0) inv[r] = 1.f / fmaxf(sqrtf(fmaxf(s, 0.f)), EPS);
    }
}

__global__ __launch_bounds__(256) void s_kernel(const float* __restrict__ wk) {
    const int bh = blockIdx.x;
    const int b = bh >> 3;
    const int h = bh & 7;
    const int tid = threadIdx.x;

    __shared__ float qs[CH][68];
    __shared__ float ks[CH][68];

    const int c0 = (tid >> 4) * 3;
    const int d0 = (tid & 15) * 3;

    float acc[3][3];
#pragma unroll
    for (int i = 0; i < 3; ++i)
#pragma unroll
        for (int j = 0; j < 3; ++j) acc[i][j] = 0.f;

    const float* Rq = g_Rq + (size_t)b * CDIM * CDIM + (size_t)(h * CH) * CDIM;
    const float* Wk = wk + (size_t)(h * CH) * CDIM;

    for (int ck = 0; ck < 6; ++ck) {
        const int koff = ck * 64;
#pragma unroll
        for (int t = 0; t < 3; ++t) {
            int idx = t * 256 + tid;
            int row = idx >> 4;
            int col = (idx & 15) * 4;
            *(float4*)&qs[row][col] = *(const float4*)(Rq + (size_t)row * CDIM + koff + col);
            *(float4*)&ks[row][col] = *(const float4*)(Wk + (size_t)row * CDIM + koff + col);
        }
        __syncthreads();
#pragma unroll 8
        for (int kk = 0; kk < 64; ++kk) {
            float q0 = qs[c0 + 0][kk], q1 = qs[c0 + 1][kk], q2 = qs[c0 + 2][kk];
            float k0 = ks[d0 + 0][kk], k1 = ks[d0 + 1][kk], k2 = ks[d0 + 2][kk];
            acc[0][0] = fmaf(q0, k0, acc[0][0]);
            acc[0][1] = fmaf(q0, k1, acc[0][1]);
            acc[0][2] = fmaf(q0, k2, acc[0][2]);
            acc[1][0] = fmaf(q1, k0, acc[1][0]);
            acc[1][1] = fmaf(q1, k1, acc[1][1]);
            acc[1][2] = fmaf(q1, k2, acc[1][2]);
            acc[2][0] = fmaf(q2, k0, acc[2][0]);
            acc[2][1] = fmaf(q2, k1, acc[2][1]);
            acc[2][2] = fmaf(q2, k2, acc[2][2]);
        }
        __syncthreads();
    }

    float* Sb = g_S + (size_t)bh * CH * CH;
#pragma unroll
    for (int i = 0; i < 3; ++i)
#pragma unroll
        for (int j = 0; j < 3; ++j)
            Sb[(c0 + i) * CH + (d0 + j)] = acc[i][j];
}

__global__ void attn_softmax_kernel(const float* __restrict__ temperature) {
    const int bh = blockIdx.x;
    const int b = bh >> 3;
    const int h = bh & 7;
    const int c = threadIdx.x;
    if (c >= CH) return;

    const float t = temperature[h];
    const float sq = g_invq[b * CDIM + h * CH + c] * t;
    const float* Srow = g_S + (size_t)bh * CH * CH + c * CH;
    const float* ik = g_invk + b * CDIM + h * CH;

    float v[CH];
    float m = -1e30f;
#pragma unroll
    for (int d = 0; d < CH; ++d) {
        v[d] = Srow[d] * sq * ik[d];
        m = fmaxf(m, v[d]);
    }
    float sum = 0.f;
#pragma unroll
    for (int d = 0; d < CH; ++d) {
        v[d] = __expf(v[d] - m);
        sum += v[d];
    }
    float inv = 1.f / sum;
    float* Arow = g_A + (size_t)bh * CH * CH + c * CH;
#pragma unroll
    for (int d = 0; d < CH; ++d) Arow[d] = v[d] * inv;
}

__global__ __launch_bounds__(384) void bstack_T(const float* __restrict__ wv) {
    const int bh = blockIdx.x;
    const int b = bh >> 3;
    const int h = bh & 7;

    __shared__ float As[CH * CH];
    const float* Ahp = g_A + (size_t)bh * CH * CH;
    for (int i = threadIdx.x; i < CH * CH; i += 384) As[i] = Ahp[i];
    __syncthreads();

    const int m = threadIdx.x;
    float acc[CH];
#pragma unroll
    for (int i = 0; i < CH; ++i) acc[i] = 0.f;

    const float* wvp = wv + (size_t)(h * CH) * CDIM + m;
    for (int d = 0; d < CH; ++d) {
        float wvv = wvp[(size_t)d * CDIM];
#pragma unroll
        for (int cp = 0; cp < CH; ++cp) acc[cp] = fmaf(As[cp * CH + d], wvv, acc[cp]);
    }
    size_t base = ((size_t)b * CDIM + m) * CDIM + h * CH;
    __align__(16) __nv_bfloat16 hh[CH], ll[CH];
#pragma unroll
    for (int cp = 0; cp < CH; ++cp) {
        __nv_bfloat16 hv = __float2bfloat16(acc[cp]);
        hh[cp] = hv;
        ll[cp] = __float2bfloat16(acc[cp] - __bfloat162float(hv));
    }
#pragma unroll
    for (int q = 0; q < CH / 4; ++q) {
        *(uint2*)(g_BsThi + base + q * 4) = *(const uint2*)(hh + q * 4);
        *(uint2*)(g_BsTlo + base + q * 4) = *(const uint2*)(ll + q * 4);
    }
}

// ---------------- launcher ----------------
extern "C" void kernel_launch(void* const* d_in, const int* in_sizes, int n_in,
                              void* d_out, int out_size) {
    const float* x    = (const float*)d_in[0];
    const float* wq   = (const float*)d_in[1];
    const float* wk   = (const float*)d_in[2];
    const float* wv   = (const float*)d_in[3];
    const float* wo   = (const float*)d_in[4];
    const float* temp = (const float*)d_in[5];
    float* out = (float*)d_out;

    cudaFuncSetAttribute(syrk_mma, cudaFuncAttributeMaxDynamicSharedMemorySize, PIPE_SMEM);
    cudaFuncSetAttribute(wgemm_mma, cudaFuncAttributeMaxDynamicSharedMemorySize, PIPE_SMEM);
    cudaFuncSetAttribute(out_mma, cudaFuncAttributeMaxDynamicSharedMemorySize, OUT_SMEM);

    const size_t CC = (size_t)CDIM * CDIM;
    const int nG = (int)(((size_t)BATCH * CC + 255) / 256);

    convert_plain<<<24576, 256>>>(x);
    convert_W<<<(CDIM * CDIM + 255) / 256, 256>>>(wq, wk, wo);
    zero_G_kernel<<<nG, 256>>>();
    syrk_mma<<<dim3(6, 16, BATCH), 256, PIPE_SMEM>>>();
    mirror_convert_G<<<nG, 256>>>();

    wgemm_mma<<<dim3(9, BATCH, 2), 256, PIPE_SMEM>>>(0);   // Rq, Rk

    norms_kernel<<<dim3(2, BATCH), 384>>>(wq, wk);
    s_kernel<<<BATCH * NHEAD, 256>>>(wk);
    attn_softmax_kernel<<<BATCH * NHEAD, 64>>>(temp);
    bstack_T<<<BATCH * NHEAD, 384>>>(wv);

    wgemm_mma<<<dim3(9, BATCH, 1), 256, PIPE_SMEM>>>(1);   // Mhi/Mlo

    out_mma<<<dim3(HW / 128, 3, BATCH), 256, OUT_SMEM>>>(out);
}